// round 2
// baseline (speedup 1.0000x reference)
#include <cuda_runtime.h>
#include <math.h>

#define B_    8
#define T_    2048
#define DIN   512
#define DA    8
#define DOUT  512

__device__ __align__(16) float g_Q[B_ * T_ * DA];
__device__ __align__(16) float g_K[B_ * T_ * DA];
__device__ __align__(16) float g_V[B_ * T_ * DOUT];

// ---------------------------------------------------------------------------
// f32x2 packed helpers (Blackwell dual-issue fp32 path, PTX-only)
// ---------------------------------------------------------------------------
__device__ __forceinline__ unsigned long long pack2(float lo, float hi) {
    unsigned long long d;
    asm("mov.b64 %0, {%1, %2};" : "=l"(d) : "f"(lo), "f"(hi));
    return d;
}
__device__ __forceinline__ unsigned long long fma2(unsigned long long a,
                                                   unsigned long long b,
                                                   unsigned long long c) {
    unsigned long long d;
    asm("fma.rn.f32x2 %0, %1, %2, %3;" : "=l"(d) : "l"(a), "l"(b), "l"(c));
    return d;
}
__device__ __forceinline__ void unpack2(unsigned long long v, float& lo, float& hi) {
    asm("mov.b64 {%0, %1}, %2;" : "=f"(lo), "=f"(hi) : "l"(v));
}

// ---------------------------------------------------------------------------
// Kernel 1: Q,K projections. One warp per 4 tokens (amortize W loads 4x).
// grid = B_*T_/32 CTAs of 256 threads (8 warps x 4 tokens).
// ---------------------------------------------------------------------------
__global__ __launch_bounds__(256) void qk_kernel(const float* __restrict__ X,
                                                 const float* __restrict__ Wq,
                                                 const float* __restrict__ Wk) {
    int warp = threadIdx.x >> 5;
    int lane = threadIdx.x & 31;
    int tok0 = blockIdx.x * 32 + warp * 4;

    float aq[4][8], ak[4][8];
#pragma unroll
    for (int t = 0; t < 4; t++)
#pragma unroll
        for (int f = 0; f < 8; f++) { aq[t][f] = 0.f; ak[t][f] = 0.f; }

#pragma unroll 4
    for (int d = lane; d < DIN; d += 32) {
        float xv[4];
#pragma unroll
        for (int t = 0; t < 4; t++) xv[t] = X[(size_t)(tok0 + t) * DIN + d];
        float4 q0 = *(const float4*)(Wq + (size_t)d * 8);
        float4 q1 = *(const float4*)(Wq + (size_t)d * 8 + 4);
        float4 k0 = *(const float4*)(Wk + (size_t)d * 8);
        float4 k1 = *(const float4*)(Wk + (size_t)d * 8 + 4);
#pragma unroll
        for (int t = 0; t < 4; t++) {
            aq[t][0] += xv[t] * q0.x; aq[t][1] += xv[t] * q0.y;
            aq[t][2] += xv[t] * q0.z; aq[t][3] += xv[t] * q0.w;
            aq[t][4] += xv[t] * q1.x; aq[t][5] += xv[t] * q1.y;
            aq[t][6] += xv[t] * q1.z; aq[t][7] += xv[t] * q1.w;
            ak[t][0] += xv[t] * k0.x; ak[t][1] += xv[t] * k0.y;
            ak[t][2] += xv[t] * k0.z; ak[t][3] += xv[t] * k0.w;
            ak[t][4] += xv[t] * k1.x; ak[t][5] += xv[t] * k1.y;
            ak[t][6] += xv[t] * k1.z; ak[t][7] += xv[t] * k1.w;
        }
    }

#pragma unroll
    for (int t = 0; t < 4; t++) {
#pragma unroll
        for (int f = 0; f < 8; f++) {
#pragma unroll
            for (int off = 16; off >= 1; off >>= 1) {
                aq[t][f] += __shfl_xor_sync(0xffffffffu, aq[t][f], off);
                ak[t][f] += __shfl_xor_sync(0xffffffffu, ak[t][f], off);
            }
        }
        if (lane == 0) {
            float* qo = g_Q + (size_t)(tok0 + t) * 8;
            float* ko = g_K + (size_t)(tok0 + t) * 8;
            *(float4*)(qo)     = make_float4(aq[t][0], aq[t][1], aq[t][2], aq[t][3]);
            *(float4*)(qo + 4) = make_float4(aq[t][4], aq[t][5], aq[t][6], aq[t][7]);
            *(float4*)(ko)     = make_float4(ak[t][0], ak[t][1], ak[t][2], ak[t][3]);
            *(float4*)(ko + 4) = make_float4(ak[t][4], ak[t][5], ak[t][6], ak[t][7]);
        }
    }
}

// ---------------------------------------------------------------------------
// Kernel 2: V = X @ Wv. BM=BN=128, BK=16, 256 threads, 8x8 micro-tile done
// as 4 packed-f32x2 row pairs x 8 cols (fma.rn.f32x2: 2x fp32 FMA rate).
// ---------------------------------------------------------------------------
__global__ __launch_bounds__(256) void vproj_kernel(const float* __restrict__ A,
                                                    const float* __restrict__ Bw) {
    __shared__ float As[16][132];
    __shared__ float Bs[16][128];

    int t  = threadIdx.x;
    int bm = blockIdx.y;
    int bn = blockIdx.x;
    int tr = t >> 4;
    int tc = t & 15;

    const float* Ag = A + (size_t)bm * 128 * DIN;
    const float* Bg = Bw + (size_t)bn * 128;

    unsigned long long acc2[4][8];
#pragma unroll
    for (int p = 0; p < 4; p++)
#pragma unroll
        for (int j = 0; j < 8; j++) acc2[p][j] = 0ull;

    for (int kt = 0; kt < DIN; kt += 16) {
#pragma unroll
        for (int e = t; e < 512; e += 256) {
            int row = e >> 2;
            int cg  = (e & 3) << 2;
            float4 v = *(const float4*)(Ag + (size_t)row * DIN + kt + cg);
            As[cg + 0][row] = v.x;
            As[cg + 1][row] = v.y;
            As[cg + 2][row] = v.z;
            As[cg + 3][row] = v.w;
        }
#pragma unroll
        for (int e = t; e < 512; e += 256) {
            int row = e >> 5;
            int cg  = (e & 31) << 2;
            *(float4*)(&Bs[row][cg]) =
                *(const float4*)(Bg + (size_t)(kt + row) * DOUT + cg);
        }
        __syncthreads();

#pragma unroll
        for (int k = 0; k < 16; k++) {
            ulonglong2 a01 = *(const ulonglong2*)(&As[k][tr * 4]);
            ulonglong2 a23 = *(const ulonglong2*)(&As[k][tr * 4 + 64]);
            float4 bA = *(const float4*)(&Bs[k][tc * 4]);
            float4 bB = *(const float4*)(&Bs[k][tc * 4 + 64]);
            unsigned long long a2[4] = {a01.x, a01.y, a23.x, a23.y};
            unsigned long long b2[8];
            b2[0] = pack2(bA.x, bA.x); b2[1] = pack2(bA.y, bA.y);
            b2[2] = pack2(bA.z, bA.z); b2[3] = pack2(bA.w, bA.w);
            b2[4] = pack2(bB.x, bB.x); b2[5] = pack2(bB.y, bB.y);
            b2[6] = pack2(bB.z, bB.z); b2[7] = pack2(bB.w, bB.w);
#pragma unroll
            for (int p = 0; p < 4; p++)
#pragma unroll
                for (int j = 0; j < 8; j++)
                    acc2[p][j] = fma2(a2[p], b2[j], acc2[p][j]);
        }
        __syncthreads();
    }

#pragma unroll
    for (int p = 0; p < 4; p++) {
        int r0 = tr * 4 + (p >> 1) * 64 + (p & 1) * 2;   // rows r0 (lo), r0+1 (hi)
        float lo[8], hi[8];
#pragma unroll
        for (int j = 0; j < 8; j++) unpack2(acc2[p][j], lo[j], hi[j]);
        float* c0 = g_V + (size_t)(bm * 128 + r0) * DOUT + bn * 128;
        float* c1 = c0 + DOUT;
        *(float4*)(c0 + tc * 4)      = make_float4(lo[0], lo[1], lo[2], lo[3]);
        *(float4*)(c0 + tc * 4 + 64) = make_float4(lo[4], lo[5], lo[6], lo[7]);
        *(float4*)(c1 + tc * 4)      = make_float4(hi[0], hi[1], hi[2], hi[3]);
        *(float4*)(c1 + tc * 4 + 64) = make_float4(hi[4], hi[5], hi[6], hi[7]);
    }
}

// ---------------------------------------------------------------------------
// Kernel 3: sparse-softmax attention.
// grid = B_*T_/32 CTAs; each CTA stages its batch's K (transposed [8][2048])
// in 64KB smem, 8 warps x 4 queries. Pass 1: s8 for all keys kept in
// registers (fully unrolled), row max. Pass 2: only keys with s8 > m-23
// (p > 1e-10) contribute; exp computed once per surviving key.
// Dropped mass <= 2048 * 1e-10 (identical in numerator & denominator).
// ---------------------------------------------------------------------------
__global__ __launch_bounds__(256) void attn_kernel(float* __restrict__ Out) {
    extern __shared__ float Kt[];   // [8][2048]
    int tid  = threadIdx.x;
    int warp = tid >> 5;
    int lane = tid & 31;
    int q0   = blockIdx.x * 32;
    int b    = q0 >> 11;
    const float* Kb = g_K + (size_t)b * T_ * DA;
    const float* Vb = g_V + (size_t)b * T_ * DOUT;

    // Stage K transposed: Kt[f][s]
    for (int idx = tid; idx < 4096; idx += 256) {
        int row = idx >> 1;
        int h   = (idx & 1) * 4;
        float4 v = *(const float4*)(Kb + (size_t)row * 8 + h);
        Kt[(h + 0) * 2048 + row] = v.x;
        Kt[(h + 1) * 2048 + row] = v.y;
        Kt[(h + 2) * 2048 + row] = v.z;
        Kt[(h + 3) * 2048 + row] = v.w;
    }
    __syncthreads();

#pragma unroll 1
    for (int qi = 0; qi < 4; qi++) {
        int q = q0 + warp * 4 + qi;
        float qv[8];
#pragma unroll
        for (int f = 0; f < 8; f++) qv[f] = g_Q[(size_t)q * 8 + f];

        float s8v[64];
        float m = -INFINITY;
#pragma unroll
        for (int i = 0; i < 64; i++) {
            int s = i * 32 + lane;
            float d = 0.f;
#pragma unroll
            for (int f = 0; f < 8; f++) d += qv[f] * Kt[f * 2048 + s];
            float d2 = d * d;
            float d4 = d2 * d2;
            float d8 = d4 * d4;
            s8v[i] = d8;
            m = fmaxf(m, d8);
        }
#pragma unroll
        for (int off = 16; off >= 1; off >>= 1)
            m = fmaxf(m, __shfl_xor_sync(0xffffffffu, m, off));

        float thr = m - 23.0f;   // exp(-23) ~ 1e-10
        float acc[16];
#pragma unroll
        for (int j = 0; j < 16; j++) acc[j] = 0.f;
        float psum = 0.f;

#pragma unroll
        for (int i = 0; i < 64; i++) {
            unsigned ball = __ballot_sync(0xffffffffu, s8v[i] > thr);
            while (ball) {
                int src = __ffs(ball) - 1;
                ball &= ball - 1;
                float d8s = __shfl_sync(0xffffffffu, s8v[i], src);
                float p = __expf(d8s - m);   // identical in all lanes
                psum += p;
                int s = i * 32 + src;
                const float4* vp = (const float4*)(Vb + (size_t)s * DOUT) + lane * 4;
                float4 v0 = vp[0];
                float4 v1 = vp[1];
                float4 v2 = vp[2];
                float4 v3 = vp[3];
                acc[0]  += p * v0.x; acc[1]  += p * v0.y; acc[2]  += p * v0.z; acc[3]  += p * v0.w;
                acc[4]  += p * v1.x; acc[5]  += p * v1.y; acc[6]  += p * v1.z; acc[7]  += p * v1.w;
                acc[8]  += p * v2.x; acc[9]  += p * v2.y; acc[10] += p * v2.z; acc[11] += p * v2.w;
                acc[12] += p * v3.x; acc[13] += p * v3.y; acc[14] += p * v3.z; acc[15] += p * v3.w;
            }
        }

        float inv = 1.f / psum;
        float4* op = (float4*)(Out + (size_t)q * DOUT) + lane * 4;
        op[0] = make_float4(acc[0]  * inv, acc[1]  * inv, acc[2]  * inv, acc[3]  * inv);
        op[1] = make_float4(acc[4]  * inv, acc[5]  * inv, acc[6]  * inv, acc[7]  * inv);
        op[2] = make_float4(acc[8]  * inv, acc[9]  * inv, acc[10] * inv, acc[11] * inv);
        op[3] = make_float4(acc[12] * inv, acc[13] * inv, acc[14] * inv, acc[15] * inv);
    }
}

// ---------------------------------------------------------------------------
extern "C" void kernel_launch(void* const* d_in, const int* in_sizes, int n_in,
                              void* d_out, int out_size) {
    (void)in_sizes; (void)n_in; (void)out_size;
    const float* X  = (const float*)d_in[0];
    const float* Wq = (const float*)d_in[1];
    const float* Wk = (const float*)d_in[2];
    const float* Wv = (const float*)d_in[3];
    float* Out = (float*)d_out;

    cudaFuncSetAttribute(attn_kernel,
                         cudaFuncAttributeMaxDynamicSharedMemorySize, 65536);

    qk_kernel<<<(B_ * T_) / 32, 256>>>(X, Wq, Wk);
    vproj_kernel<<<dim3(DOUT / 128, (B_ * T_) / 128), 256>>>(X, Wv);
    attn_kernel<<<(B_ * T_) / 32, 256, 65536>>>(Out);
}